// round 1
// baseline (speedup 1.0000x reference)
#include <cuda_runtime.h>
#include <math.h>

#define EMB   1024
#define DK    64
#define BATCH 4
#define SEQ   4096
#define MROWS (BATCH * SEQ)   // 16384

// ---------------- scratch (allocation-free) ----------------
__device__ float g_q[MROWS * DK];
__device__ float g_k[MROWS * DK];
__device__ float g_v[MROWS * DK];

// ---------------- projection GEMM ----------------
// C[M,64] = X[M,1024] @ W[1024,64] + bias ; blockIdx.z selects (Q|K|V)
#define PBK 16

__global__ __launch_bounds__(256) void proj_kernel(
    const float* __restrict__ in1, const float* __restrict__ in2,
    const float* __restrict__ Wq, const float* __restrict__ bq,
    const float* __restrict__ Wk, const float* __restrict__ bk,
    const float* __restrict__ Wv, const float* __restrict__ bv)
{
    __shared__ float As[PBK][68];   // [k][m] transposed A tile
    __shared__ float Bs[PBK][68];   // [k][n]

    const int which = blockIdx.z;
    const float* X    = (which == 0) ? in2 : in1;
    const float* W    = (which == 0) ? Wq : (which == 1 ? Wk : Wv);
    const float* bias = (which == 0) ? bq : (which == 1 ? bk : bv);
    float* dst        = (which == 0) ? g_q : (which == 1 ? g_k : g_v);

    const int m0  = blockIdx.x * 64;
    const int tid = threadIdx.x;
    const int tx  = tid & 15;      // 0..15 -> N
    const int ty  = tid >> 4;      // 0..15 -> M

    float acc[4][4];
    #pragma unroll
    for (int i = 0; i < 4; i++)
        #pragma unroll
        for (int j = 0; j < 4; j++) acc[i][j] = 0.f;

    const int ar = tid >> 2;            // 0..63 row of A tile
    const int ak = (tid & 3) * 4;       // 0,4,8,12 within k-tile
    const int br = tid >> 4;            // 0..15 k-row of B tile
    const int bc = (tid & 15) * 4;      // 0..60 col

    for (int kt = 0; kt < EMB; kt += PBK) {
        float4 a = *(const float4*)(X + (size_t)(m0 + ar) * EMB + kt + ak);
        As[ak + 0][ar] = a.x;
        As[ak + 1][ar] = a.y;
        As[ak + 2][ar] = a.z;
        As[ak + 3][ar] = a.w;
        *(float4*)&Bs[br][bc] = *(const float4*)(W + (size_t)(kt + br) * DK + bc);
        __syncthreads();

        #pragma unroll
        for (int k = 0; k < PBK; k++) {
            float4 av = *(const float4*)&As[k][ty * 4];
            float4 bv4 = *(const float4*)&Bs[k][tx * 4];
            float af[4] = {av.x, av.y, av.z, av.w};
            float bf[4] = {bv4.x, bv4.y, bv4.z, bv4.w};
            #pragma unroll
            for (int i = 0; i < 4; i++)
                #pragma unroll
                for (int j = 0; j < 4; j++)
                    acc[i][j] = fmaf(af[i], bf[j], acc[i][j]);
        }
        __syncthreads();
    }

    float4 bb = *(const float4*)(bias + tx * 4);
    float bbf[4] = {bb.x, bb.y, bb.z, bb.w};
    #pragma unroll
    for (int i = 0; i < 4; i++) {
        const int row = m0 + ty * 4 + i;
        float4 o;
        o.x = acc[i][0] + bbf[0];
        o.y = acc[i][1] + bbf[1];
        o.z = acc[i][2] + bbf[2];
        o.w = acc[i][3] + bbf[3];
        *(float4*)(dst + (size_t)row * DK + tx * 4) = o;
    }
}

// ---------------- flash attention ----------------
// Per block: one (batch, 64-query tile). Stream 64-key tiles with online softmax.
#define BQ  64
#define BKV 64
#define SPITCH 68   // float pitch: float4-aligned, <=2-way LDS conflicts

__global__ __launch_bounds__(256, 2) void flash_kernel(float* __restrict__ out)
{
    extern __shared__ float sm[];
    float* Qs = sm;                      // [64][68] q-major
    float* Ks = Qs + BQ * SPITCH;        // [64][68] key-major
    float* Vs = Ks + BKV * SPITCH;       // [64][68] key-major
    float* Ps = Vs + BKV * SPITCH;       // [64][68] q-major

    const int b   = blockIdx.y;
    const int q0  = blockIdx.x * BQ;
    const int tid = threadIdx.x;
    const int tx  = tid & 15;            // -> key cols / d cols (x4)
    const int ty  = tid >> 4;            // -> q rows (x4)
    const float scale = 0.125f;          // 1/sqrt(64)

    // load Q tile (pre-scaled)
    const float* Qg = g_q + (size_t)(b * SEQ + q0) * DK;
    #pragma unroll
    for (int i = tid; i < BQ * (DK / 4); i += 256) {
        int r = i >> 4, c4 = (i & 15) * 4;
        float4 v = *(const float4*)(Qg + (size_t)r * DK + c4);
        v.x *= scale; v.y *= scale; v.z *= scale; v.w *= scale;
        *(float4*)(Qs + r * SPITCH + c4) = v;
    }

    float m_i[4], l_i[4], acc[4][4];
    #pragma unroll
    for (int i = 0; i < 4; i++) {
        m_i[i] = -INFINITY; l_i[i] = 0.f;
        #pragma unroll
        for (int j = 0; j < 4; j++) acc[i][j] = 0.f;
    }

    for (int kt = 0; kt < SEQ; kt += BKV) {
        const float* Kg = g_k + (size_t)(b * SEQ + kt) * DK;
        const float* Vg = g_v + (size_t)(b * SEQ + kt) * DK;
        __syncthreads();   // prev iter done reading Ks/Vs/Ps
        #pragma unroll
        for (int i = tid; i < BKV * (DK / 4); i += 256) {
            int r = i >> 4, c4 = (i & 15) * 4;
            *(float4*)(Ks + r * SPITCH + c4) = *(const float4*)(Kg + (size_t)r * DK + c4);
            *(float4*)(Vs + r * SPITCH + c4) = *(const float4*)(Vg + (size_t)r * DK + c4);
        }
        __syncthreads();

        // ---- S = Qs . Ks^T  (dot-product micro-tile: 8 LDS.128 / 64 FMA) ----
        float s[4][4];
        #pragma unroll
        for (int i = 0; i < 4; i++)
            #pragma unroll
            for (int j = 0; j < 4; j++) s[i][j] = 0.f;

        #pragma unroll 4
        for (int d4 = 0; d4 < DK; d4 += 4) {
            float qf[16], kf[16];
            #pragma unroll
            for (int i = 0; i < 4; i++)
                *(float4*)&qf[i * 4] = *(const float4*)(Qs + (ty * 4 + i) * SPITCH + d4);
            #pragma unroll
            for (int j = 0; j < 4; j++)
                *(float4*)&kf[j * 4] = *(const float4*)(Ks + (tx * 4 + j) * SPITCH + d4);
            #pragma unroll
            for (int i = 0; i < 4; i++)
                #pragma unroll
                for (int j = 0; j < 4; j++)
                    #pragma unroll
                    for (int c = 0; c < 4; c++)
                        s[i][j] = fmaf(qf[i * 4 + c], kf[j * 4 + c], s[i][j]);
        }

        // ---- online softmax (per q-row; reduce across the 16 tx lanes) ----
        #pragma unroll
        for (int i = 0; i < 4; i++) {
            float mx = fmaxf(fmaxf(s[i][0], s[i][1]), fmaxf(s[i][2], s[i][3]));
            mx = fmaxf(mx, __shfl_xor_sync(0xffffffffu, mx, 8));
            mx = fmaxf(mx, __shfl_xor_sync(0xffffffffu, mx, 4));
            mx = fmaxf(mx, __shfl_xor_sync(0xffffffffu, mx, 2));
            mx = fmaxf(mx, __shfl_xor_sync(0xffffffffu, mx, 1));
            const float mnew = fmaxf(m_i[i], mx);
            const float corr = __expf(m_i[i] - mnew);
            float ssum = 0.f;
            float p[4];
            #pragma unroll
            for (int j = 0; j < 4; j++) {
                p[j] = __expf(s[i][j] - mnew);
                ssum += p[j];
            }
            ssum += __shfl_xor_sync(0xffffffffu, ssum, 8);
            ssum += __shfl_xor_sync(0xffffffffu, ssum, 4);
            ssum += __shfl_xor_sync(0xffffffffu, ssum, 2);
            ssum += __shfl_xor_sync(0xffffffffu, ssum, 1);
            l_i[i] = l_i[i] * corr + ssum;
            m_i[i] = mnew;
            #pragma unroll
            for (int j = 0; j < 4; j++) acc[i][j] *= corr;
            float4 pv = {p[0], p[1], p[2], p[3]};
            *(float4*)(Ps + (ty * 4 + i) * SPITCH + tx * 4) = pv;
        }
        __syncthreads();   // Ps visible to all

        // ---- acc += Ps . Vs  (rank-1 over k, 8 LDS.128 / 64 FMA) ----
        #pragma unroll 4
        for (int k4 = 0; k4 < BKV; k4 += 4) {
            float pf[16], vf[16];
            #pragma unroll
            for (int i = 0; i < 4; i++)
                *(float4*)&pf[i * 4] = *(const float4*)(Ps + (ty * 4 + i) * SPITCH + k4);
            #pragma unroll
            for (int kk = 0; kk < 4; kk++)
                *(float4*)&vf[kk * 4] = *(const float4*)(Vs + (k4 + kk) * SPITCH + tx * 4);
            #pragma unroll
            for (int i = 0; i < 4; i++)
                #pragma unroll
                for (int j = 0; j < 4; j++)
                    #pragma unroll
                    for (int kk = 0; kk < 4; kk++)
                        acc[i][j] = fmaf(pf[i * 4 + kk], vf[kk * 4 + j], acc[i][j]);
        }
    }

    // ---- epilogue: normalize and store ----
    #pragma unroll
    for (int i = 0; i < 4; i++) {
        const float inv_l = 1.f / l_i[i];
        const size_t row = (size_t)(b * SEQ + q0 + ty * 4 + i);
        float4 o;
        o.x = acc[i][0] * inv_l;
        o.y = acc[i][1] * inv_l;
        o.z = acc[i][2] * inv_l;
        o.w = acc[i][3] * inv_l;
        *(float4*)(out + row * DK + tx * 4) = o;
    }
}

// ---------------- launch ----------------
extern "C" void kernel_launch(void* const* d_in, const int* in_sizes, int n_in,
                              void* d_out, int out_size)
{
    const float* input1 = (const float*)d_in[0];
    const float* input2 = (const float*)d_in[1];
    const float* Wq = (const float*)d_in[2];
    const float* bq = (const float*)d_in[3];
    const float* Wk = (const float*)d_in[4];
    const float* bk = (const float*)d_in[5];
    const float* Wv = (const float*)d_in[6];
    const float* bv = (const float*)d_in[7];
    float* out = (float*)d_out;

    (void)in_sizes; (void)n_in; (void)out_size;

    // Projections: Q from input2; K,V from input1
    dim3 pgrid(MROWS / 64, 1, 3);
    proj_kernel<<<pgrid, 256>>>(input1, input2, Wq, bq, Wk, bk, Wv, bv);

    // Flash attention
    const int smem_bytes = 4 * BQ * SPITCH * (int)sizeof(float);  // 69632
    cudaFuncSetAttribute(flash_kernel,
                         cudaFuncAttributeMaxDynamicSharedMemorySize, smem_bytes);
    dim3 fgrid(SEQ / BQ, BATCH);
    flash_kernel<<<fgrid, 256, smem_bytes>>>(out);
}

// round 3
// speedup vs baseline: 3.9432x; 3.9432x over previous
#include <cuda_runtime.h>
#include <math.h>
#include <stdint.h>

#define EMB   1024
#define DK    64
#define BATCH 4
#define SEQ   4096
#define MROWS (BATCH * SEQ)   // 16384

// ---------------- scratch (allocation-free) ----------------
__device__ float g_q[MROWS * DK];   // [row][d]
__device__ float g_k[MROWS * DK];   // [row][d]
__device__ float g_v[MROWS * DK];   // [row][d]

// ---------------- helpers ----------------
__device__ __forceinline__ uint32_t f2tf(float f) {
    uint32_t u;
    asm("cvt.rna.tf32.f32 %0, %1;" : "=r"(u) : "f"(f));
    return u;
}

// D = A(16x8, row) * B(8x8, col) + D, tf32 inputs, f32 accum
__device__ __forceinline__ void mma8(float* c, const uint32_t* a,
                                     uint32_t b0, uint32_t b1) {
    asm volatile(
        "mma.sync.aligned.m16n8k8.row.col.f32.tf32.tf32.f32 "
        "{%0,%1,%2,%3}, {%4,%5,%6,%7}, {%8,%9}, {%0,%1,%2,%3};"
        : "+f"(c[0]), "+f"(c[1]), "+f"(c[2]), "+f"(c[3])
        : "r"(a[0]), "r"(a[1]), "r"(a[2]), "r"(a[3]), "r"(b0), "r"(b1));
}

// ============================================================
// Projection GEMM: C[16384,64] = X[16384,1024] @ W[1024,64] + b
// blockIdx.z selects Q|K|V.  BM=128, BN=64, BK=32, 8 warps.
// ============================================================
#define XS_P 36   // Xs pitch: A-frag banks (4g + 8ks + t4) distinct
#define WS_P 72   // Ws pitch: B-frag banks (8*t4 + g) distinct

__global__ __launch_bounds__(256, 1) void proj_mma(
    const float* __restrict__ in1, const float* __restrict__ in2,
    const float* __restrict__ Wq, const float* __restrict__ bq,
    const float* __restrict__ Wk, const float* __restrict__ bk,
    const float* __restrict__ Wv, const float* __restrict__ bv)
{
    __shared__ float Xs[128][XS_P];
    __shared__ float Ws[32][WS_P];

    const int which = blockIdx.z;
    const float* X    = (which == 0) ? in2 : in1;
    const float* W    = (which == 0) ? Wq : (which == 1 ? Wk : Wv);
    const float* bias = (which == 0) ? bq : (which == 1 ? bk : bv);
    float* dst        = (which == 0) ? g_q : (which == 1 ? g_k : g_v);

    const int m0   = blockIdx.x * 128;
    const int tid  = threadIdx.x;
    const int warp = tid >> 5;
    const int lane = tid & 31;
    const int g    = lane >> 2;      // 0..7
    const int t4   = lane & 3;       // 0..3
    const int wm   = warp * 16;

    float acc[8][4];
    #pragma unroll
    for (int nt = 0; nt < 8; nt++)
        #pragma unroll
        for (int j = 0; j < 4; j++) acc[nt][j] = 0.f;

    for (int kt = 0; kt < EMB; kt += 32) {
        // load X tile 128x32 (tf32-rounded)
        #pragma unroll
        for (int it = 0; it < 4; it++) {
            int idx = tid + it * 256;           // 1024 float4
            int r = idx >> 3, c4 = (idx & 7) * 4;
            float4 v = *(const float4*)(X + (size_t)(m0 + r) * EMB + kt + c4);
            Xs[r][c4 + 0] = __uint_as_float(f2tf(v.x));
            Xs[r][c4 + 1] = __uint_as_float(f2tf(v.y));
            Xs[r][c4 + 2] = __uint_as_float(f2tf(v.z));
            Xs[r][c4 + 3] = __uint_as_float(f2tf(v.w));
        }
        // load W tile 32x64
        #pragma unroll
        for (int it = 0; it < 2; it++) {
            int idx = tid + it * 256;           // 512 float4
            int r = idx >> 4, c4 = (idx & 15) * 4;
            float4 v = *(const float4*)(W + (size_t)(kt + r) * DK + c4);
            Ws[r][c4 + 0] = __uint_as_float(f2tf(v.x));
            Ws[r][c4 + 1] = __uint_as_float(f2tf(v.y));
            Ws[r][c4 + 2] = __uint_as_float(f2tf(v.z));
            Ws[r][c4 + 3] = __uint_as_float(f2tf(v.w));
        }
        __syncthreads();

        #pragma unroll
        for (int ks = 0; ks < 4; ks++) {
            uint32_t a[4];
            a[0] = __float_as_uint(Xs[wm + g    ][ks * 8 + t4    ]);
            a[1] = __float_as_uint(Xs[wm + g + 8][ks * 8 + t4    ]);
            a[2] = __float_as_uint(Xs[wm + g    ][ks * 8 + t4 + 4]);
            a[3] = __float_as_uint(Xs[wm + g + 8][ks * 8 + t4 + 4]);
            #pragma unroll
            for (int nt = 0; nt < 8; nt++) {
                uint32_t b0 = __float_as_uint(Ws[ks * 8 + t4    ][nt * 8 + g]);
                uint32_t b1 = __float_as_uint(Ws[ks * 8 + t4 + 4][nt * 8 + g]);
                mma8(acc[nt], a, b0, b1);
            }
        }
        __syncthreads();
    }

    // epilogue: + bias, store
    #pragma unroll
    for (int nt = 0; nt < 8; nt++) {
        const int col = nt * 8 + 2 * t4;
        const float b0 = bias[col], b1 = bias[col + 1];
        const int rowA = m0 + wm + g, rowB = rowA + 8;
        float2 oa = {acc[nt][0] + b0, acc[nt][1] + b1};
        float2 ob = {acc[nt][2] + b0, acc[nt][3] + b1};
        *(float2*)(dst + (size_t)rowA * DK + col) = oa;
        *(float2*)(dst + (size_t)rowB * DK + col) = ob;
    }
}

// ============================================================
// Flash attention, tf32 mma.sync
// CTA: 256 thr (8 warps x 16 q-rows = 128 q). KV tiles of 64.
// ============================================================
#define KS_P 68   // K_s pitch: B-frag banks (4g + t4) distinct
#define VS_P 72   // V_s pitch: B-frag banks (8*t4 + g) distinct
#define PS_P 68   // P_s pitch: A-frag banks (4g + t4) distinct

#define KS_OFF 0
#define VS_OFF (64 * KS_P)              // 4352
#define PS_OFF (VS_OFF + 64 * VS_P)     // 8960
#define SM_FLOATS (PS_OFF + 128 * PS_P) // 17664
#define SM_BYTES (SM_FLOATS * 4)        // 70656

__global__ __launch_bounds__(256, 1) void flash_mma(float* __restrict__ out)
{
    extern __shared__ float sm[];
    float* Ks = sm + KS_OFF;
    float* Vs = sm + VS_OFF;
    float* Ps = sm + PS_OFF;

    const int tid  = threadIdx.x;
    const int warp = tid >> 5;
    const int lane = tid & 31;
    const int g    = lane >> 2;
    const int t4   = lane & 3;
    const int wm   = warp * 16;
    const int b    = blockIdx.y;
    const int q0   = blockIdx.x * 128;

    // ---- Q fragments in registers (pre-scaled, tf32) ----
    uint32_t q[32];
    {
        const float* Qg = g_q + (size_t)(b * SEQ + q0 + wm) * DK;
        #pragma unroll
        for (int ks = 0; ks < 8; ks++) {
            q[ks * 4 + 0] = f2tf(0.125f * Qg[(size_t)(g    ) * DK + ks * 8 + t4    ]);
            q[ks * 4 + 1] = f2tf(0.125f * Qg[(size_t)(g + 8) * DK + ks * 8 + t4    ]);
            q[ks * 4 + 2] = f2tf(0.125f * Qg[(size_t)(g    ) * DK + ks * 8 + t4 + 4]);
            q[ks * 4 + 3] = f2tf(0.125f * Qg[(size_t)(g + 8) * DK + ks * 8 + t4 + 4]);
        }
    }

    float o[8][4];
    #pragma unroll
    for (int nt = 0; nt < 8; nt++)
        #pragma unroll
        for (int j = 0; j < 4; j++) o[nt][j] = 0.f;
    float mA = -INFINITY, mB = -INFINITY, lA = 0.f, lB = 0.f;

    for (int kt = 0; kt < SEQ; kt += 64) {
        __syncthreads();   // previous tile's K/V reads complete

        // ---- load K,V tiles [64 keys][64 d] (tf32-rounded) ----
        const float* Kg = g_k + (size_t)(b * SEQ + kt) * DK;
        const float* Vg = g_v + (size_t)(b * SEQ + kt) * DK;
        #pragma unroll
        for (int it = 0; it < 4; it++) {
            int idx = tid + it * 256;           // 1024 float4
            int r = idx >> 4, c4 = (idx & 15) * 4;
            float4 kv = *(const float4*)(Kg + (size_t)r * DK + c4);
            Ks[r * KS_P + c4 + 0] = __uint_as_float(f2tf(kv.x));
            Ks[r * KS_P + c4 + 1] = __uint_as_float(f2tf(kv.y));
            Ks[r * KS_P + c4 + 2] = __uint_as_float(f2tf(kv.z));
            Ks[r * KS_P + c4 + 3] = __uint_as_float(f2tf(kv.w));
            float4 vv = *(const float4*)(Vg + (size_t)r * DK + c4);
            Vs[r * VS_P + c4 + 0] = __uint_as_float(f2tf(vv.x));
            Vs[r * VS_P + c4 + 1] = __uint_as_float(f2tf(vv.y));
            Vs[r * VS_P + c4 + 2] = __uint_as_float(f2tf(vv.z));
            Vs[r * VS_P + c4 + 3] = __uint_as_float(f2tf(vv.w));
        }
        __syncthreads();

        // ---- S = Q @ K^T : s[nt] covers keys nt*8..nt*8+7 ----
        float s[8][4];
        #pragma unroll
        for (int nt = 0; nt < 8; nt++)
            #pragma unroll
            for (int j = 0; j < 4; j++) s[nt][j] = 0.f;

        #pragma unroll
        for (int ks = 0; ks < 8; ks++) {
            #pragma unroll
            for (int nt = 0; nt < 8; nt++) {
                uint32_t b0 = __float_as_uint(Ks[(nt * 8 + g) * KS_P + ks * 8 + t4    ]);
                uint32_t b1 = __float_as_uint(Ks[(nt * 8 + g) * KS_P + ks * 8 + t4 + 4]);
                mma8(s[nt], &q[ks * 4], b0, b1);
            }
        }

        // ---- online softmax (rows g / g+8, quad reductions) ----
        float mxA = -INFINITY, mxB = -INFINITY;
        #pragma unroll
        for (int nt = 0; nt < 8; nt++) {
            mxA = fmaxf(mxA, fmaxf(s[nt][0], s[nt][1]));
            mxB = fmaxf(mxB, fmaxf(s[nt][2], s[nt][3]));
        }
        mxA = fmaxf(mxA, __shfl_xor_sync(0xffffffffu, mxA, 1));
        mxA = fmaxf(mxA, __shfl_xor_sync(0xffffffffu, mxA, 2));
        mxB = fmaxf(mxB, __shfl_xor_sync(0xffffffffu, mxB, 1));
        mxB = fmaxf(mxB, __shfl_xor_sync(0xffffffffu, mxB, 2));

        const float mnA = fmaxf(mA, mxA), mnB = fmaxf(mB, mxB);
        const float cA = __expf(mA - mnA), cB = __expf(mB - mnB);

        float sumA = 0.f, sumB = 0.f;
        #pragma unroll
        for (int nt = 0; nt < 8; nt++) {
            s[nt][0] = __expf(s[nt][0] - mnA);
            s[nt][1] = __expf(s[nt][1] - mnA);
            s[nt][2] = __expf(s[nt][2] - mnB);
            s[nt][3] = __expf(s[nt][3] - mnB);
            sumA += s[nt][0] + s[nt][1];
            sumB += s[nt][2] + s[nt][3];
        }
        sumA += __shfl_xor_sync(0xffffffffu, sumA, 1);
        sumA += __shfl_xor_sync(0xffffffffu, sumA, 2);
        sumB += __shfl_xor_sync(0xffffffffu, sumB, 1);
        sumB += __shfl_xor_sync(0xffffffffu, sumB, 2);
        lA = lA * cA + sumA;  mA = mnA;
        lB = lB * cB + sumB;  mB = mnB;

        // rescale O
        #pragma unroll
        for (int nt = 0; nt < 8; nt++) {
            o[nt][0] *= cA; o[nt][1] *= cA;
            o[nt][2] *= cB; o[nt][3] *= cB;
        }

        // ---- P -> warp-private smem (tf32) ----
        #pragma unroll
        for (int nt = 0; nt < 8; nt++) {
            const int col = nt * 8 + 2 * t4;
            uint2 pa = {f2tf(s[nt][0]), f2tf(s[nt][1])};
            uint2 pb = {f2tf(s[nt][2]), f2tf(s[nt][3])};
            *(uint2*)(Ps + (wm + g    ) * PS_P + col) = pa;
            *(uint2*)(Ps + (wm + g + 8) * PS_P + col) = pb;
        }
        __syncwarp();

        // ---- O += P @ V ----
        #pragma unroll
        for (int ks = 0; ks < 8; ks++) {
            uint32_t a[4];
            a[0] = __float_as_uint(Ps[(wm + g    ) * PS_P + ks * 8 + t4    ]);
            a[1] = __float_as_uint(Ps[(wm + g + 8) * PS_P + ks * 8 + t4    ]);
            a[2] = __float_as_uint(Ps[(wm + g    ) * PS_P + ks * 8 + t4 + 4]);
            a[3] = __float_as_uint(Ps[(wm + g + 8) * PS_P + ks * 8 + t4 + 4]);
            #pragma unroll
            for (int nt = 0; nt < 8; nt++) {
                uint32_t b0 = __float_as_uint(Vs[(ks * 8 + t4    ) * VS_P + nt * 8 + g]);
                uint32_t b1 = __float_as_uint(Vs[(ks * 8 + t4 + 4) * VS_P + nt * 8 + g]);
                mma8(o[nt], a, b0, b1);
            }
        }
    }

    // ---- epilogue ----
    const float ilA = 1.f / lA, ilB = 1.f / lB;
    const int rowA = b * SEQ + q0 + wm + g;
    const int rowB = rowA + 8;
    #pragma unroll
    for (int nt = 0; nt < 8; nt++) {
        const int col = nt * 8 + 2 * t4;
        float2 oa = {o[nt][0] * ilA, o[nt][1] * ilA};
        float2 ob = {o[nt][2] * ilB, o[nt][3] * ilB};
        *(float2*)(out + (size_t)rowA * DK + col) = oa;
        *(float2*)(out + (size_t)rowB * DK + col) = ob;
    }
}

// ---------------- launch ----------------
extern "C" void kernel_launch(void* const* d_in, const int* in_sizes, int n_in,
                              void* d_out, int out_size)
{
    const float* input1 = (const float*)d_in[0];
    const float* input2 = (const float*)d_in[1];
    const float* Wq = (const float*)d_in[2];
    const float* bq = (const float*)d_in[3];
    const float* Wk = (const float*)d_in[4];
    const float* bk = (const float*)d_in[5];
    const float* Wv = (const float*)d_in[6];
    const float* bv = (const float*)d_in[7];
    float* out = (float*)d_out;

    (void)in_sizes; (void)n_in; (void)out_size;

    dim3 pgrid(MROWS / 128, 1, 3);
    proj_mma<<<pgrid, 256>>>(input1, input2, Wq, bq, Wk, bk, Wv, bv);

    cudaFuncSetAttribute(flash_mma, cudaFuncAttributeMaxDynamicSharedMemorySize, SM_BYTES);
    dim3 fgrid(SEQ / 128, BATCH);
    flash_mma<<<fgrid, 256, SM_BYTES>>>(out);
}